// round 1
// baseline (speedup 1.0000x reference)
#include <cuda_runtime.h>
#include <cuda_bf16.h>

#define ALPHA_MARGIN 1.0f

// One warp per pair. X row = 256 floats: a = [0,128), b = [128,256).
// Lane i loads float4 a[4i..] and float4 b[4i..] (two coalesced 512B chunks
// per warp), computes partial sum of squared diffs, butterfly-reduces,
// lane 0 applies the adj selection and writes the loss.
__global__ __launch_bounds__(256) void contrastive_loss_kernel(
    const float* __restrict__ X,
    const int*   __restrict__ y,
    float*       __restrict__ out,
    int n_pairs)
{
    int warp = (blockIdx.x * blockDim.x + threadIdx.x) >> 5;
    int lane = threadIdx.x & 31;
    if (warp >= n_pairs) return;

    const float4* row = reinterpret_cast<const float4*>(X) + (size_t)warp * 64;
    float4 a = __ldg(row + lane);        // a: float4 index [0,32)
    float4 b = __ldg(row + 32 + lane);   // b: float4 index [32,64)

    float dx = a.x - b.x;
    float dy = a.y - b.y;
    float dz = a.z - b.z;
    float dw = a.w - b.w;
    float s = dx * dx + dy * dy + dz * dz + dw * dw;

    #pragma unroll
    for (int o = 16; o > 0; o >>= 1)
        s += __shfl_xor_sync(0xffffffffu, s, o);

    if (lane == 0) {
        int adj = y[warp];
        float loss;
        if (adj == 1)       loss = s;
        else if (adj == 0)  loss = fmaxf(ALPHA_MARGIN - s, 0.0f);
        else                loss = 0.0f;
        out[warp] = loss;
    }
}

extern "C" void kernel_launch(void* const* d_in, const int* in_sizes, int n_in,
                              void* d_out, int out_size)
{
    const float* X = (const float*)d_in[0];
    const int*   y = (const int*)d_in[1];
    float*       out = (float*)d_out;

    int n_pairs = out_size;              // B * N * N = 524288
    int warps_per_block = 256 / 32;      // 8
    int blocks = (n_pairs + warps_per_block - 1) / warps_per_block;

    contrastive_loss_kernel<<<blocks, 256>>>(X, y, out, n_pairs);
}

// round 2
// speedup vs baseline: 1.1306x; 1.1306x over previous
#include <cuda_runtime.h>
#include <cuda_bf16.h>

#define ALPHA_MARGIN 1.0f

// Persistent grid-stride kernel. Each warp processes 2 pairs per iteration
// (4 x LDG.128 per lane-group, fully coalesced 512B chunks), with the next
// iteration's loads prefetched before the current reduction so memory stays
// saturated through the SHFL chain.
__global__ __launch_bounds__(256) void contrastive_loss_kernel(
    const float* __restrict__ X,
    const int*   __restrict__ y,
    float*       __restrict__ out,
    int n_pairs)
{
    const int lane   = threadIdx.x & 31;
    const int gwarp  = (blockIdx.x * blockDim.x + threadIdx.x) >> 5;
    const int nwarps = (gridDim.x * blockDim.x) >> 5;

    // Each iteration handles 2 consecutive pairs per warp.
    const int stride = nwarps * 2;
    int p = gwarp * 2;

    const float4* Xv = reinterpret_cast<const float4*>(X);

    // Prologue: load iteration 0
    float4 a0, b0, a1, b1;
    if (p < n_pairs) {
        const float4* r0 = Xv + (size_t)p * 64;
        a0 = __ldg(r0 + lane);
        b0 = __ldg(r0 + 32 + lane);
    }
    if (p + 1 < n_pairs) {
        const float4* r1 = Xv + (size_t)(p + 1) * 64;
        a1 = __ldg(r1 + lane);
        b1 = __ldg(r1 + 32 + lane);
    }

    while (p < n_pairs) {
        int pn = p + stride;

        // Prefetch next iteration before reducing current
        float4 na0, nb0, na1, nb1;
        bool have_n0 = (pn     < n_pairs);
        bool have_n1 = (pn + 1 < n_pairs);
        if (have_n0) {
            const float4* r0 = Xv + (size_t)pn * 64;
            na0 = __ldg(r0 + lane);
            nb0 = __ldg(r0 + 32 + lane);
        }
        if (have_n1) {
            const float4* r1 = Xv + (size_t)(pn + 1) * 64;
            na1 = __ldg(r1 + lane);
            nb1 = __ldg(r1 + 32 + lane);
        }

        // Compute pair p
        {
            float dx = a0.x - b0.x, dy = a0.y - b0.y;
            float dz = a0.z - b0.z, dw = a0.w - b0.w;
            float s = dx * dx + dy * dy + dz * dz + dw * dw;
            #pragma unroll
            for (int o = 16; o > 0; o >>= 1)
                s += __shfl_xor_sync(0xffffffffu, s, o);
            if (lane == 0) {
                int adj = y[p];
                float loss = (adj == 1) ? s
                           : (adj == 0) ? fmaxf(ALPHA_MARGIN - s, 0.0f)
                           : 0.0f;
                out[p] = loss;
            }
        }

        // Compute pair p+1
        if (p + 1 < n_pairs) {
            float dx = a1.x - b1.x, dy = a1.y - b1.y;
            float dz = a1.z - b1.z, dw = a1.w - b1.w;
            float s = dx * dx + dy * dy + dz * dz + dw * dw;
            #pragma unroll
            for (int o = 16; o > 0; o >>= 1)
                s += __shfl_xor_sync(0xffffffffu, s, o);
            if (lane == 0) {
                int adj = y[p + 1];
                float loss = (adj == 1) ? s
                           : (adj == 0) ? fmaxf(ALPHA_MARGIN - s, 0.0f)
                           : 0.0f;
                out[p + 1] = loss;
            }
        }

        a0 = na0; b0 = nb0; a1 = na1; b1 = nb1;
        p = pn;
    }
}

extern "C" void kernel_launch(void* const* d_in, const int* in_sizes, int n_in,
                              void* d_out, int out_size)
{
    const float* X = (const float*)d_in[0];
    const int*   y = (const int*)d_in[1];
    float*       out = (float*)d_out;

    int n_pairs = out_size;      // B*N*N = 524288
    int blocks  = 2048;          // persistent-ish: ~13 CTAs/SM worth of warps
    contrastive_loss_kernel<<<blocks, 256>>>(X, y, out, n_pairs);
}